// round 2
// baseline (speedup 1.0000x reference)
#include <cuda_runtime.h>
#include <cuda_bf16.h>

#define IN_F 128
#define HID 128
#define NCTX 32
#define ALPHA 0.2f
#define NEG_INF -9000000000000000.0f
#define MAXN 20000

// Scratch (device globals — no allocation allowed)
__device__ __align__(16) float g_u_i[IN_F];       // W_i @ a_i
__device__ __align__(16) float g_u_j[IN_F];       // W_j @ a_j
__device__ float g_bias;
__device__ float g_s_i[MAXN];
__device__ float g_s_j[MAXN];
__device__ __align__(16) float g_feat[(size_t)MAXN * HID]; // attn-weighted feature sums

// ---------------------------------------------------------------------------
// K1: fold attention vectors through the weight matrices.
// u_i[f] = sum_h W_i[f,h] * a_w[h];  u_j[f] = sum_h W_j[f,h] * a_w[128+h]
// ---------------------------------------------------------------------------
__global__ void prep_kernel(const float* __restrict__ W_i,
                            const float* __restrict__ W_j,
                            const float* __restrict__ a_w,
                            const float* __restrict__ a_b) {
    int t = threadIdx.x;  // 0..127
    float ai = 0.f, aj = 0.f;
    #pragma unroll 8
    for (int h = 0; h < HID; h++) {
        ai += W_i[t * HID + h] * a_w[h];
        aj += W_j[t * HID + h] * a_w[HID + h];
    }
    g_u_i[t] = ai;
    g_u_j[t] = aj;
    if (t == 0) g_bias = a_b[0];
}

// ---------------------------------------------------------------------------
// K2: per-node scalar scores. One warp per node.
// s_i[n] = h[n] . u_i ;  s_j[n] = h[n] . u_j
// ---------------------------------------------------------------------------
__global__ void score_kernel(const float* __restrict__ h_i, int N) {
    int warp = blockIdx.x * (blockDim.x >> 5) + (threadIdx.x >> 5);
    int lane = threadIdx.x & 31;
    if (warp >= N) return;
    const float4* h4 = (const float4*)h_i;
    float4 v  = h4[(size_t)warp * 32 + lane];
    float4 ui = ((const float4*)g_u_i)[lane];
    float4 uj = ((const float4*)g_u_j)[lane];
    float a = v.x * ui.x + v.y * ui.y + v.z * ui.z + v.w * ui.w;
    float b = v.x * uj.x + v.y * uj.y + v.z * uj.z + v.w * uj.w;
    #pragma unroll
    for (int o = 16; o; o >>= 1) {
        a += __shfl_xor_sync(0xffffffffu, a, o);
        b += __shfl_xor_sync(0xffffffffu, b, o);
    }
    if (lane == 0) {
        g_s_i[warp] = a;
        g_s_j[warp] = b;
    }
}

// ---------------------------------------------------------------------------
// K3: gather + leaky-relu + softmax + attention-weighted raw-feature sum.
// One warp per node. Lane c owns neighbor c for the logit; then each lane
// accumulates 4 feature columns over all 32 neighbors (coalesced 512B rows,
// table is L2-resident).
// ---------------------------------------------------------------------------
__global__ void gather_kernel(const float* __restrict__ h_i,
                              const int* __restrict__ ctx, int N) {
    int warp = blockIdx.x * (blockDim.x >> 5) + (threadIdx.x >> 5);
    int lane = threadIdx.x & 31;
    if (warp >= N) return;

    int j = ctx[(size_t)warp * NCTX + lane];
    bool valid = (j >= 0);

    float sj = valid ? g_s_j[j] : 0.f;
    float e = g_s_i[warp] + sj + g_bias;
    e = (e > 0.f) ? e : ALPHA * e;       // leaky relu
    e = valid ? e : NEG_INF;             // mask

    // warp softmax over 32 logits
    float m = e;
    #pragma unroll
    for (int o = 16; o; o >>= 1) m = fmaxf(m, __shfl_xor_sync(0xffffffffu, m, o));
    float p = valid ? __expf(e - m) : 0.f;
    float s = p;
    #pragma unroll
    for (int o = 16; o; o >>= 1) s += __shfl_xor_sync(0xffffffffu, s, o);
    float inv = (s > 0.f) ? (1.f / s) : 0.f;
    float w = p * inv;

    // weighted sum of raw neighbor features: lane owns columns [lane*4, lane*4+4)
    float4 acc = make_float4(0.f, 0.f, 0.f, 0.f);
    const float4* h4 = (const float4*)h_i;
    #pragma unroll
    for (int c = 0; c < NCTX; c++) {
        float wc = __shfl_sync(0xffffffffu, w, c);
        int jc   = __shfl_sync(0xffffffffu, j, c);
        if (jc >= 0) {
            float4 v = h4[(size_t)jc * 32 + lane];
            acc.x = fmaf(wc, v.x, acc.x);
            acc.y = fmaf(wc, v.y, acc.y);
            acc.z = fmaf(wc, v.z, acc.z);
            acc.w = fmaf(wc, v.w, acc.w);
        }
    }
    ((float4*)g_feat)[(size_t)warp * 32 + lane] = acc;
}

// ---------------------------------------------------------------------------
// K4: out = g_feat @ W_j   (M=N, K=128, Ncols=128), fp32 SIMT SGEMM.
// Block tile 64x128, 256 threads, per-thread micro-tile 8 rows x 4 cols.
// Smem: g tile 32KB + W k-chunk 16KB = 48KB static.
// ---------------------------------------------------------------------------
__global__ __launch_bounds__(256) void out_gemm_kernel(
    const float* __restrict__ Wj, float* __restrict__ out, int N) {
    __shared__ float gs[64][128];
    __shared__ float ws[32][128];

    int row0 = blockIdx.x * 64;
    int tid = threadIdx.x;

    // load g tile (64 rows x 128 cols) with float4
    for (int i = tid; i < 64 * 32; i += 256) {
        int r = i >> 5, c4 = i & 31;
        int gr = row0 + r;
        float4 v = make_float4(0.f, 0.f, 0.f, 0.f);
        if (gr < N) v = ((const float4*)g_feat)[(size_t)gr * 32 + c4];
        ((float4*)&gs[r][0])[c4] = v;
    }

    int cg  = tid & 31;    // col group -> cols [cg*4, cg*4+4)
    int rg  = tid >> 5;    // row group -> rows [rg*8, rg*8+8)
    int col = cg * 4;

    float acc[8][4];
    #pragma unroll
    for (int r = 0; r < 8; r++)
        #pragma unroll
        for (int q = 0; q < 4; q++) acc[r][q] = 0.f;

    for (int k0 = 0; k0 < 128; k0 += 32) {
        __syncthreads();
        // load W chunk [k0..k0+32) x 128
        for (int i = tid; i < 32 * 32; i += 256) {
            int r = i >> 5, c4 = i & 31;
            ((float4*)&ws[r][0])[c4] = ((const float4*)Wj)[(size_t)(k0 + r) * 32 + c4];
        }
        __syncthreads();
        #pragma unroll
        for (int kk = 0; kk < 32; kk++) {
            float4 wv = *(const float4*)&ws[kk][col];
            #pragma unroll
            for (int r = 0; r < 8; r++) {
                float gv = gs[rg * 8 + r][k0 + kk];   // warp-broadcast
                acc[r][0] = fmaf(gv, wv.x, acc[r][0]);
                acc[r][1] = fmaf(gv, wv.y, acc[r][1]);
                acc[r][2] = fmaf(gv, wv.z, acc[r][2]);
                acc[r][3] = fmaf(gv, wv.w, acc[r][3]);
            }
        }
    }

    #pragma unroll
    for (int r = 0; r < 8; r++) {
        int gr = row0 + rg * 8 + r;
        if (gr < N) {
            float4 o = make_float4(acc[r][0], acc[r][1], acc[r][2], acc[r][3]);
            *(float4*)&out[(size_t)gr * 128 + col] = o;
        }
    }
}

// ---------------------------------------------------------------------------
extern "C" void kernel_launch(void* const* d_in, const int* in_sizes, int n_in,
                              void* d_out, int out_size) {
    const float* h_i = (const float*)d_in[0];
    const int*   ctx = (const int*)d_in[1];     // int32 (JAX x64 disabled)
    const float* W_i = (const float*)d_in[2];
    const float* W_j = (const float*)d_in[3];
    const float* a_w = (const float*)d_in[4];
    const float* a_b = (const float*)d_in[5];
    float* out = (float*)d_out;

    int N = in_sizes[0] / IN_F;

    prep_kernel<<<1, 128>>>(W_i, W_j, a_w, a_b);

    int warps_per_block = 8;
    int blocks = (N + warps_per_block - 1) / warps_per_block;
    score_kernel<<<blocks, 256>>>(h_i, N);
    gather_kernel<<<blocks, 256>>>(h_i, ctx, N);

    int gemm_blocks = (N + 63) / 64;
    out_gemm_kernel<<<gemm_blocks, 256>>>(W_j, out, N);
}